// round 16
// baseline (speedup 1.0000x reference)
#include <cuda_runtime.h>
#include <cuda_fp16.h>
#include <cstdint>
#include <cstddef>

#define BSZ   8192
#define DIMN  100
#define NSTEP 49
#define WH    256
#define RRATE 0.05f

// ---------------- device scratch (static, no allocations) ----------------
__device__ float g_volpre[(size_t)NSTEP * BSZ * DIMN];
__device__ float g_Sbuf[2][BSZ * DIMN];
__device__ float g_hdual[2][(size_t)2 * BSZ * WH];
__device__ float g_C[(size_t)2 * BSZ * DIMN];          // gradv out: grad rows | v rows
__device__ float g_vsave[BSZ];
__device__ float g_stoch[BSZ];
__device__ float g_err[BSZ];
__device__ float g_bvout[DIMN];
// transposed weights: Wt[n*K + k] = W[k*N + n]
__device__ float g_Wgt_in[WH * DIMN];
__device__ float g_Wgt_h[3][WH * WH];
__device__ float g_Wgt_out[DIMN * WH];
__device__ float g_Wvt_out[DIMN * WH];
__device__ float g_Wvt_in[WH * DIMN];
__device__ float g_Wvt_h[3][WH * WH];

// ---------------- helpers ----------------
__device__ __forceinline__ uint32_t smem_u32(const void* p) {
    uint32_t a;
    asm("{ .reg .u64 t; cvta.to.shared.u64 t, %1; cvt.u32.u64 %0, t; }" : "=r"(a) : "l"(p));
    return a;
}
__device__ __forceinline__ void split2(float x0, float x1, uint32_t& h, uint32_t& l) {
    __half2 hh = __floats2half2_rn(x0, x1);
    float2 hf = __half22float2(hh);
    __half2 ll = __floats2half2_rn(x0 - hf.x, x1 - hf.y);
    h = *reinterpret_cast<uint32_t*>(&hh);
    l = *reinterpret_cast<uint32_t*>(&ll);
}
__device__ __forceinline__ void mma16(float d[4], const uint32_t a[4],
                                      uint32_t b0, uint32_t b1) {
    asm volatile(
        "mma.sync.aligned.m16n8k16.row.col.f32.f16.f16.f32 "
        "{%0,%1,%2,%3}, {%4,%5,%6,%7}, {%8,%9}, {%0,%1,%2,%3};"
        : "+f"(d[0]), "+f"(d[1]), "+f"(d[2]), "+f"(d[3])
        : "r"(a[0]), "r"(a[1]), "r"(a[2]), "r"(a[3]), "r"(b0), "r"(b1));
}
__device__ __forceinline__ void ldm4(uint32_t r[4], uint32_t addr) {
    asm volatile("ldmatrix.sync.aligned.m8n8.x4.shared.b16 {%0,%1,%2,%3}, [%4];"
                 : "=r"(r[0]), "=r"(r[1]), "=r"(r[2]), "=r"(r[3]) : "r"(addr));
}

// smem per buffer: rows of 16 halves, row stride 48B (conflict-free)
#define A_LO_OFF  6144
#define B_HI_OFF  12288
#define B_LO_OFF  18432
#define BUF_BYTES 24576
#define DYN_SMEM  (2 * BUF_BYTES)        // 49152, 2 CTAs/SM

// ========== R12 GEMM: fp16 3x-split, dual-weight, CTA 128x128, warp 32x64 =====
__global__ __launch_bounds__(256, 2)
void gemm_mma(const float* __restrict__ A,
              const float* __restrict__ Wt0, const float* __restrict__ Wt1,
              const float* __restrict__ bias0, const float* __restrict__ bias1,
              const float* __restrict__ w00, const float* __restrict__ w01,
              const float* __restrict__ tg, int tIdx,
              float* __restrict__ C, int N, int K, int relu,
              int halfBlocks, int wrapA)
{
    extern __shared__ uint32_t smw[];
    char* smc = (char*)smw;
    const uint32_t smemBase = smem_u32(smw);

    const int tid    = threadIdx.x;
    const int lane   = tid & 31;
    const int wid    = tid >> 5;
    const int warp_m = wid & 3;
    const int warp_n = wid >> 2;
    const int mBase  = blockIdx.y * 128;
    const int nBase  = blockIdx.x * 128;
    const bool hiH   = (int)blockIdx.y >= halfBlocks;
    const float* Wt   = hiH ? Wt1   : Wt0;
    const float* bias = hiH ? bias1 : bias0;
    const float* w0   = hiH ? w01   : w00;

    const int qrow = lane >> 2;
    const int qk   = lane & 3;

    float acc[2][8][4];
#pragma unroll
    for (int i = 0; i < 2; ++i)
#pragma unroll
        for (int j = 0; j < 8; ++j)
#pragma unroll
            for (int q = 0; q < 4; ++q) acc[i][j][q] = 0.f;

    const int r0  = tid >> 2;
    const int r1  = r0 + 64;
    const int c40 = (tid & 3) << 2;
    int ar0 = mBase + r0, ar1 = mBase + r1;
    if (wrapA) { ar0 &= (BSZ - 1); ar1 &= (BSZ - 1); }
    const int gn0 = nBase + r0, gn1 = nBase + r1;

    const int l15 = lane & 15;
    const int lc  = (lane >> 4) << 4;
    const uint32_t offA0 = (uint32_t)(warp_m * 32 + l15) * 48 + lc;
    const uint32_t offA1 = offA0 + 16 * 48;
    const uint32_t offB  = (uint32_t)B_HI_OFF + (uint32_t)(warp_n * 64 + l15) * 48 + lc;

    const int nChunks = (K + 15) >> 4;

    float4 av0, av1, bv0, bv1;
    auto prefetch = [&](int kc) {
        const int gc = (kc << 4) + c40;
        av0 = av1 = bv0 = bv1 = make_float4(0.f, 0.f, 0.f, 0.f);
        if (gc < K) {
            av0 = *(const float4*)(A + (size_t)ar0 * K + gc);
            av1 = *(const float4*)(A + (size_t)ar1 * K + gc);
            if (gn0 < N) bv0 = *(const float4*)(Wt + (size_t)gn0 * K + gc);
            if (gn1 < N) bv1 = *(const float4*)(Wt + (size_t)gn1 * K + gc);
        }
    };
    auto store = [&](int b) {
        char* buf = smc + b * BUF_BYTES;
        const uint32_t rowOff0 = (uint32_t)r0 * 48 + c40 * 2;
        const uint32_t rowOff1 = (uint32_t)r1 * 48 + c40 * 2;
        uint32_t h0, l0, h1, l1;
        split2(av0.x, av0.y, h0, l0); split2(av0.z, av0.w, h1, l1);
        *(uint2*)(buf + rowOff0)            = make_uint2(h0, h1);
        *(uint2*)(buf + A_LO_OFF + rowOff0) = make_uint2(l0, l1);
        split2(av1.x, av1.y, h0, l0); split2(av1.z, av1.w, h1, l1);
        *(uint2*)(buf + rowOff1)            = make_uint2(h0, h1);
        *(uint2*)(buf + A_LO_OFF + rowOff1) = make_uint2(l0, l1);
        split2(bv0.x, bv0.y, h0, l0); split2(bv0.z, bv0.w, h1, l1);
        *(uint2*)(buf + B_HI_OFF + rowOff0) = make_uint2(h0, h1);
        *(uint2*)(buf + B_LO_OFF + rowOff0) = make_uint2(l0, l1);
        split2(bv1.x, bv1.y, h0, l0); split2(bv1.z, bv1.w, h1, l1);
        *(uint2*)(buf + B_HI_OFF + rowOff1) = make_uint2(h0, h1);
        *(uint2*)(buf + B_LO_OFF + rowOff1) = make_uint2(l0, l1);
    };

    prefetch(0);
    store(0);

    for (int kc = 0; kc < nChunks; ++kc) {
        __syncthreads();
        const bool more = (kc + 1 < nChunks);
        if (more) prefetch(kc + 1);

        const uint32_t base = smemBase + (kc & 1) * BUF_BYTES;

        uint32_t ax0[4], ax1[4], bb[4][4];
        ldm4(ax0, base + offA0);
        ldm4(ax1, base + offA1);
#pragma unroll
        for (int t = 0; t < 4; ++t) ldm4(bb[t], base + offB + t * (16 * 48));
#pragma unroll
        for (int t = 0; t < 4; ++t) {
            mma16(acc[0][2 * t],     ax0, bb[t][0], bb[t][2]);
            mma16(acc[1][2 * t],     ax1, bb[t][0], bb[t][2]);
            mma16(acc[0][2 * t + 1], ax0, bb[t][1], bb[t][3]);
            mma16(acc[1][2 * t + 1], ax1, bb[t][1], bb[t][3]);
        }
        {
            uint32_t al0[4], al1[4];
            ldm4(al0, base + offA0 + A_LO_OFF);
            ldm4(al1, base + offA1 + A_LO_OFF);
#pragma unroll
            for (int t = 0; t < 4; ++t) {
                mma16(acc[0][2 * t],     al0, bb[t][0], bb[t][2]);
                mma16(acc[1][2 * t],     al1, bb[t][0], bb[t][2]);
                mma16(acc[0][2 * t + 1], al0, bb[t][1], bb[t][3]);
                mma16(acc[1][2 * t + 1], al1, bb[t][1], bb[t][3]);
            }
        }
#pragma unroll
        for (int t = 0; t < 4; ++t)
            ldm4(bb[t], base + offB + (B_LO_OFF - B_HI_OFF) + t * (16 * 48));
#pragma unroll
        for (int t = 0; t < 4; ++t) {
            mma16(acc[0][2 * t],     ax0, bb[t][0], bb[t][2]);
            mma16(acc[1][2 * t],     ax1, bb[t][0], bb[t][2]);
            mma16(acc[0][2 * t + 1], ax0, bb[t][1], bb[t][3]);
            mma16(acc[1][2 * t + 1], ax1, bb[t][1], bb[t][3]);
        }

        if (more) store((kc + 1) & 1);
    }

    const float tval = w0 ? __ldg(tg + tIdx) : 0.f;
#pragma unroll
    for (int jn = 0; jn < 8; ++jn) {
        int c = nBase + warp_n * 64 + jn * 8 + 2 * qk;
        if (c >= N) continue;
        float b0e = 0.f, b1e = 0.f;
        if (bias) { b0e = __ldg(bias + c); b1e = __ldg(bias + c + 1); }
        if (w0)   { b0e += tval * __ldg(w0 + c); b1e += tval * __ldg(w0 + c + 1); }
#pragma unroll
        for (int im = 0; im < 2; ++im) {
            int r = mBase + warp_m * 32 + im * 16 + qrow;
            float o00 = acc[im][jn][0] + b0e, o01 = acc[im][jn][1] + b1e;
            float o10 = acc[im][jn][2] + b0e, o11 = acc[im][jn][3] + b1e;
            if (relu) {
                o00 = fmaxf(o00, 0.f); o01 = fmaxf(o01, 0.f);
                o10 = fmaxf(o10, 0.f); o11 = fmaxf(o11, 0.f);
            }
            *(float2*)(C + (size_t)r * N + c)       = make_float2(o00, o01);
            *(float2*)(C + (size_t)(r + 8) * N + c) = make_float2(o10, o11);
        }
    }
}

// ====== L1 GEMM with fused step: computes S_new in SMEM, then GEMM on it ======
#define SNEW_STRIDE 116
#define SNEW_OFF    DYN_SMEM
#define L1_SMEM     (DYN_SMEM + 128 * SNEW_STRIDE * 4)   // 108544

__global__ __launch_bounds__(256, 2)
void gemm_l1_step(const float* __restrict__ S_old, const float* __restrict__ vp,
                  const float* __restrict__ grad, const float* __restrict__ Cv,
                  const float* __restrict__ tg, int stepIdx,
                  float* __restrict__ Snew, float* __restrict__ stoch,
                  float* __restrict__ vsave, float* __restrict__ err,
                  const float* __restrict__ Wt0, const float* __restrict__ Wt1,
                  const float* __restrict__ bias0, const float* __restrict__ bias1,
                  const float* __restrict__ w00, const float* __restrict__ w01,
                  float* __restrict__ C)
{
    extern __shared__ uint32_t smw[];
    char* smc = (char*)smw;
    const uint32_t smemBase = smem_u32(smw);
    float* snew = (float*)(smc + SNEW_OFF);

    const int tid    = threadIdx.x;
    const int lane   = tid & 31;
    const int wid    = tid >> 5;
    const int warp_m = wid & 3;
    const int warp_n = wid >> 2;
    const int mBase  = blockIdx.y * 128;
    const int rowBase = mBase & (BSZ - 1);
    const bool hiH   = (int)blockIdx.y >= 64;
    const float* Wt   = hiH ? Wt1   : Wt0;
    const float* bias = hiH ? bias1 : bias0;
    const float* w0   = hiH ? w01   : w00;
    const int nBase  = blockIdx.x * 128;
    const int qrow = lane >> 2;
    const int qk   = lane & 3;

    const bool fused = (stepIdx >= 0);

    // ------- fused step prologue: compute S_new rows into SMEM -------
    if (fused) {
        const int row  = tid >> 1;           // 0..127
        const int part = tid & 1;
        const int b    = rowBase + row;
        const bool writer = (blockIdx.x == 0) && ((int)blockIdx.y < 64);
        const float h  = tg[stepIdx + 1] - tg[stepIdx];
        const float sq = sqrtf(h);
        const float rh = RRATE * h;
        if (writer && part == 0) {
            float vC = Cv[(size_t)b * DIMN];
            if (stepIdx > 0) {
                float hp = tg[stepIdx] - tg[stepIdx - 1];
                float e = vC - vsave[b] * (1.f + RRATE * hp) - stoch[b];
                err[b] += e * e;
            }
            vsave[b] = vC;
        }
        float acc = 0.f;
        const int d0 = part * 50;
#pragma unroll 2
        for (int d = d0; d < d0 + 50; ++d) {
            float s   = S_old[(size_t)b * DIMN + d];
            float vol = s * (vp[(size_t)b * DIMN + d] * sq);
            acc += grad[(size_t)b * DIMN + d] * vol;
            float sn = s + rh * s + vol;
            snew[row * SNEW_STRIDE + d] = sn;
            if (writer) Snew[(size_t)b * DIMN + d] = sn;
        }
        acc += __shfl_xor_sync(0xffffffffu, acc, 1);
        if (writer && part == 0) stoch[b] = acc;
        __syncthreads();
    }

    // ------- GEMM: A = snew (fused) or S_old (initial), K=100, N=256 -------
    float acc[2][8][4];
#pragma unroll
    for (int i = 0; i < 2; ++i)
#pragma unroll
        for (int j = 0; j < 8; ++j)
#pragma unroll
            for (int q = 0; q < 4; ++q) acc[i][j][q] = 0.f;

    const int r0  = tid >> 2;
    const int r1  = r0 + 64;
    const int c40 = (tid & 3) << 2;
    const int ar0 = rowBase + r0, ar1 = rowBase + r1;
    const int gn0 = nBase + r0, gn1 = nBase + r1;

    const int l15 = lane & 15;
    const int lc  = (lane >> 4) << 4;
    const uint32_t offA0 = (uint32_t)(warp_m * 32 + l15) * 48 + lc;
    const uint32_t offA1 = offA0 + 16 * 48;
    const uint32_t offB  = (uint32_t)B_HI_OFF + (uint32_t)(warp_n * 64 + l15) * 48 + lc;

    const int nChunks = (DIMN + 15) >> 4;   // 7

    float4 av0, av1, bv0, bv1;
    auto prefetch = [&](int kc) {
        const int gc = (kc << 4) + c40;
        av0 = av1 = bv0 = bv1 = make_float4(0.f, 0.f, 0.f, 0.f);
        if (gc < DIMN) {
            if (fused) {
                av0 = *(const float4*)(snew + (size_t)r0 * SNEW_STRIDE + gc);
                av1 = *(const float4*)(snew + (size_t)r1 * SNEW_STRIDE + gc);
            } else {
                av0 = *(const float4*)(S_old + (size_t)ar0 * DIMN + gc);
                av1 = *(const float4*)(S_old + (size_t)ar1 * DIMN + gc);
            }
            bv0 = *(const float4*)(Wt + (size_t)gn0 * DIMN + gc);
            bv1 = *(const float4*)(Wt + (size_t)gn1 * DIMN + gc);
        }
    };
    auto store = [&](int b) {
        char* buf = smc + b * BUF_BYTES;
        const uint32_t rowOff0 = (uint32_t)r0 * 48 + c40 * 2;
        const uint32_t rowOff1 = (uint32_t)r1 * 48 + c40 * 2;
        uint32_t h0, l0, h1, l1;
        split2(av0.x, av0.y, h0, l0); split2(av0.z, av0.w, h1, l1);
        *(uint2*)(buf + rowOff0)            = make_uint2(h0, h1);
        *(uint2*)(buf + A_LO_OFF + rowOff0) = make_uint2(l0, l1);
        split2(av1.x, av1.y, h0, l0); split2(av1.z, av1.w, h1, l1);
        *(uint2*)(buf + rowOff1)            = make_uint2(h0, h1);
        *(uint2*)(buf + A_LO_OFF + rowOff1) = make_uint2(l0, l1);
        split2(bv0.x, bv0.y, h0, l0); split2(bv0.z, bv0.w, h1, l1);
        *(uint2*)(buf + B_HI_OFF + rowOff0) = make_uint2(h0, h1);
        *(uint2*)(buf + B_LO_OFF + rowOff0) = make_uint2(l0, l1);
        split2(bv1.x, bv1.y, h0, l0); split2(bv1.z, bv1.w, h1, l1);
        *(uint2*)(buf + B_HI_OFF + rowOff1) = make_uint2(h0, h1);
        *(uint2*)(buf + B_LO_OFF + rowOff1) = make_uint2(l0, l1);
    };

    prefetch(0);
    store(0);

    for (int kc = 0; kc < nChunks; ++kc) {
        __syncthreads();
        const bool more = (kc + 1 < nChunks);
        if (more) prefetch(kc + 1);

        const uint32_t base = smemBase + (kc & 1) * BUF_BYTES;
        uint32_t ax0[4], ax1[4], bb[4][4];
        ldm4(ax0, base + offA0);
        ldm4(ax1, base + offA1);
#pragma unroll
        for (int t = 0; t < 4; ++t) ldm4(bb[t], base + offB + t * (16 * 48));
#pragma unroll
        for (int t = 0; t < 4; ++t) {
            mma16(acc[0][2 * t],     ax0, bb[t][0], bb[t][2]);
            mma16(acc[1][2 * t],     ax1, bb[t][0], bb[t][2]);
            mma16(acc[0][2 * t + 1], ax0, bb[t][1], bb[t][3]);
            mma16(acc[1][2 * t + 1], ax1, bb[t][1], bb[t][3]);
        }
        {
            uint32_t al0[4], al1[4];
            ldm4(al0, base + offA0 + A_LO_OFF);
            ldm4(al1, base + offA1 + A_LO_OFF);
#pragma unroll
            for (int t = 0; t < 4; ++t) {
                mma16(acc[0][2 * t],     al0, bb[t][0], bb[t][2]);
                mma16(acc[1][2 * t],     al1, bb[t][0], bb[t][2]);
                mma16(acc[0][2 * t + 1], al0, bb[t][1], bb[t][3]);
                mma16(acc[1][2 * t + 1], al1, bb[t][1], bb[t][3]);
            }
        }
#pragma unroll
        for (int t = 0; t < 4; ++t)
            ldm4(bb[t], base + offB + (B_LO_OFF - B_HI_OFF) + t * (16 * 48));
#pragma unroll
        for (int t = 0; t < 4; ++t) {
            mma16(acc[0][2 * t],     ax0, bb[t][0], bb[t][2]);
            mma16(acc[1][2 * t],     ax1, bb[t][0], bb[t][2]);
            mma16(acc[0][2 * t + 1], ax0, bb[t][1], bb[t][3]);
            mma16(acc[1][2 * t + 1], ax1, bb[t][1], bb[t][3]);
        }

        if (more) store((kc + 1) & 1);
    }

    // epilogue (relu, t-fold, N=256)
    const float tval = __ldg(tg + stepIdx + 1);
#pragma unroll
    for (int jn = 0; jn < 8; ++jn) {
        int c = nBase + warp_n * 64 + jn * 8 + 2 * qk;
        float b0e = __ldg(bias + c)     + tval * __ldg(w0 + c);
        float b1e = __ldg(bias + c + 1) + tval * __ldg(w0 + c + 1);
#pragma unroll
        for (int im = 0; im < 2; ++im) {
            int r = mBase + warp_m * 32 + im * 16 + qrow;
            float o00 = fmaxf(acc[im][jn][0] + b0e, 0.f);
            float o01 = fmaxf(acc[im][jn][1] + b1e, 0.f);
            float o10 = fmaxf(acc[im][jn][2] + b0e, 0.f);
            float o11 = fmaxf(acc[im][jn][3] + b1e, 0.f);
            *(float2*)(C + (size_t)r * WH + c)       = make_float2(o00, o01);
            *(float2*)(C + (size_t)(r + 8) * WH + c) = make_float2(o10, o11);
        }
    }
}

// ---------------- fused weight transposes (ONE launch) ----------------
#define WT_TOTAL (25600 * 2 + 196608 * 2 + 25600 * 2 + DIMN)
__global__ void wtrans_all(const float* __restrict__ Wg_in, const float* __restrict__ Wv_in,
                           const float* __restrict__ Wg_h,  const float* __restrict__ Wv_h,
                           const float* __restrict__ Wg_out, const float* __restrict__ Wv_out,
                           const float* __restrict__ bv_out)
{
    for (int i = blockIdx.x * blockDim.x + threadIdx.x; i < WT_TOTAL;
         i += gridDim.x * blockDim.x) {
        int j = i;
        if (j < 25600) {
            int n = j / 100, k = j % 100;
            g_Wgt_in[j] = Wg_in[(size_t)(k + 1) * WH + n];
        } else if ((j -= 25600) < 25600) {
            int n = j / 100, k = j % 100;
            g_Wvt_in[j] = Wv_in[(size_t)(k + 1) * WH + n];
        } else if ((j -= 25600) < 196608) {
            int l = j / 65536, r = j % 65536;
            int n = r / 256, k = r % 256;
            (&g_Wgt_h[0][0])[j] = Wg_h[(size_t)l * 65536 + (size_t)k * WH + n];
        } else if ((j -= 196608) < 196608) {
            int l = j / 65536, r = j % 65536;
            int n = r / 256, k = r % 256;
            (&g_Wvt_h[0][0])[j] = Wv_h[(size_t)l * 65536 + (size_t)k * WH + n];
        } else if ((j -= 196608) < 25600) {
            int n = j / 256, k = j % 256;
            g_Wgt_out[j] = Wg_out[(size_t)k * DIMN + n];
        } else if ((j -= 25600) < 25600) {
            int n = j / 256, k = j % 256;
            g_Wvt_out[j] = (n == 0) ? Wv_out[k] : 0.f;
        } else {
            j -= 25600;
            g_bvout[j] = (j == 0) ? bv_out[0] : 0.f;
        }
    }
}

// ---------------- output packing + final error term ----------------
__global__ void pack_kernel(const float* __restrict__ Cv, const float* __restrict__ S,
                            const float* __restrict__ vsave, const float* __restrict__ stoch,
                            const float* __restrict__ tg, const float* __restrict__ err,
                            float* __restrict__ out)
{
    int i = blockIdx.x * 256 + threadIdx.x;
    if (i < BSZ * DIMN) out[BSZ + i] = S[i];
    if (i < BSZ) {
        float vC = Cv[(size_t)i * DIMN];
        float hp = tg[NSTEP] - tg[NSTEP - 1];
        float e = vC - vsave[i] * (1.f + RRATE * hp) - stoch[i];
        out[i] = vC;
        out[BSZ + BSZ * DIMN + i] = err[i] + e * e;
    }
}

extern "C" void kernel_launch(void* const* d_in, const int* in_sizes, int n_in,
                              void* d_out, int out_size)
{
    const float* S0     = (const float*)d_in[0];
    const float* dW     = (const float*)d_in[1];
    const float* tg     = (const float*)d_in[2];
    const float* Vm     = (const float*)d_in[3];
    const float* Wg_in  = (const float*)d_in[4];
    const float* bg_in  = (const float*)d_in[5];
    const float* Wg_h   = (const float*)d_in[6];
    const float* bg_h   = (const float*)d_in[7];
    const float* Wg_out = (const float*)d_in[8];
    const float* bg_out = (const float*)d_in[9];
    const float* Wv_in  = (const float*)d_in[10];
    const float* bv_in  = (const float*)d_in[11];
    const float* Wv_h   = (const float*)d_in[12];
    const float* bv_h   = (const float*)d_in[13];
    const float* Wv_out = (const float*)d_in[14];
    const float* bv_out = (const float*)d_in[15];

    cudaFuncSetAttribute(gemm_l1_step, cudaFuncAttributeMaxDynamicSharedMemorySize,
                         L1_SMEM);

    float *volpre, *Sb, *hd, *Cbuf, *vsave, *stoch, *err, *bvout;
    float *Wgt_in, *Wgt_h, *Wgt_out, *Wvt_out, *Wvt_in, *Wvt_h;
    cudaGetSymbolAddress((void**)&volpre, g_volpre);
    cudaGetSymbolAddress((void**)&Sb,     g_Sbuf);
    cudaGetSymbolAddress((void**)&hd,     g_hdual);
    cudaGetSymbolAddress((void**)&Cbuf,   g_C);
    cudaGetSymbolAddress((void**)&vsave,  g_vsave);
    cudaGetSymbolAddress((void**)&stoch,  g_stoch);
    cudaGetSymbolAddress((void**)&err,    g_err);
    cudaGetSymbolAddress((void**)&bvout,  g_bvout);
    cudaGetSymbolAddress((void**)&Wgt_in, g_Wgt_in);
    cudaGetSymbolAddress((void**)&Wgt_h,  g_Wgt_h);
    cudaGetSymbolAddress((void**)&Wgt_out,g_Wgt_out);
    cudaGetSymbolAddress((void**)&Wvt_out,g_Wvt_out);
    cudaGetSymbolAddress((void**)&Wvt_in, g_Wvt_in);
    cudaGetSymbolAddress((void**)&Wvt_h,  g_Wvt_h);

    float* Sbuf0 = Sb;
    float* Sbuf1 = Sb + (size_t)BSZ * DIMN;
    float* hA = hd;
    float* hB = hd + (size_t)2 * BSZ * WH;
    float* Cv = Cbuf + (size_t)BSZ * DIMN;

    // launch 0: weight transposes
    wtrans_all<<<512, 256>>>(Wg_in, Wv_in, Wg_h, Wv_h, Wg_out, Wv_out, bv_out);

    // launch 1: volpre = dW @ V^T
    {
        dim3 grid(1, (NSTEP * BSZ) / 128);
        gemm_mma<<<grid, 256, DYN_SMEM>>>(dW, Vm, Vm, nullptr, nullptr,
                                          nullptr, nullptr, nullptr, 0,
                                          volpre, DIMN, DIMN, 0, 1 << 30, 0);
    }

    auto hidden3 = [&]() {
        dim3 grid(2, 128);
        gemm_mma<<<grid, 256, DYN_SMEM>>>(hA, Wgt_h, Wvt_h, bg_h, bv_h,
                                          nullptr, nullptr, nullptr, 0,
                                          hB, WH, WH, 1, 64, 0);
        gemm_mma<<<grid, 256, DYN_SMEM>>>(hB, Wgt_h + 65536, Wvt_h + 65536,
                                          bg_h + WH, bv_h + WH,
                                          nullptr, nullptr, nullptr, 0,
                                          hA, WH, WH, 1, 64, 0);
        gemm_mma<<<grid, 256, DYN_SMEM>>>(hA, Wgt_h + 2 * 65536, Wvt_h + 2 * 65536,
                                          bg_h + 2 * WH, bv_h + 2 * WH,
                                          nullptr, nullptr, nullptr, 0,
                                          hB, WH, WH, 1, 64, 0);
    };
    auto gradv = [&]() {
        dim3 grid(1, 128);
        gemm_mma<<<grid, 256, DYN_SMEM>>>(hB, Wgt_out, Wvt_out, bg_out, bvout,
                                          nullptr, nullptr, nullptr, 0,
                                          Cbuf, DIMN, WH, 0, 64, 0);
    };
    auto l1 = [&](const float* Sold, const float* vp, int stepIdx, float* Snew) {
        dim3 grid(2, 128);
        gemm_l1_step<<<grid, 256, L1_SMEM>>>(Sold, vp, Cbuf, Cv, tg, stepIdx,
                                             Snew, stoch, vsave, err,
                                             Wgt_in, Wvt_in, bg_in, bv_in,
                                             Wg_in, Wv_in, hA);
    };

    // initial trunk on [t0, S0]
    l1(S0, nullptr, -1, nullptr);
    hidden3();
    gradv();                                      // grad_0, v_0
    cudaMemsetAsync(err, 0, BSZ * sizeof(float));

    const float* Scur = S0;
    int sflip = 0;
    for (int i = 0; i < NSTEP; ++i) {
        float* Snew = sflip ? Sbuf1 : Sbuf0;
        // fused: step i (S update, stoch_i, err_{i-1}, vsave=v_i) + L1 GEMM on S_{i+1}
        l1(Scur, volpre + (size_t)i * BSZ * DIMN, i, Snew);
        hidden3();
        gradv();                                  // grad_{i+1}, v_{i+1}
        Scur = Snew; sflip ^= 1;
    }

    pack_kernel<<<(BSZ * DIMN) / 256, 256>>>(Cv, Scur, vsave, stoch, tg, err,
                                             (float*)d_out);
}

// round 17
// speedup vs baseline: 1.4053x; 1.4053x over previous
#include <cuda_runtime.h>
#include <cuda_fp16.h>
#include <cstdint>
#include <cstddef>

#define BSZ   8192
#define DIMN  100
#define NSTEP 49
#define WH    256
#define RRATE 0.05f

// ---------------- device scratch (static, no allocations) ----------------
__device__ float g_volpre[(size_t)NSTEP * BSZ * DIMN];
__device__ float g_Sbuf[2][BSZ * DIMN];
__device__ float g_hdual[2][(size_t)2 * BSZ * WH];     // dual-MLP activations [16384][256]
__device__ float g_C[(size_t)2 * BSZ * DIMN];          // gradv out: grad rows | v rows
__device__ float g_vsave[BSZ];
__device__ float g_stoch[BSZ];
__device__ float g_err[BSZ];
__device__ float g_bvout[DIMN];
// transposed weights: Wt[n*K + k] = W[k*N + n]
__device__ float g_Wgt_in[WH * DIMN];
__device__ float g_Wgt_h[3][WH * WH];
__device__ float g_Wgt_out[DIMN * WH];
__device__ float g_Wvt_out[DIMN * WH];
__device__ float g_Wvt_in[WH * DIMN];
__device__ float g_Wvt_h[3][WH * WH];

// ---------------- helpers ----------------
__device__ __forceinline__ uint32_t smem_u32(const void* p) {
    uint32_t a;
    asm("{ .reg .u64 t; cvta.to.shared.u64 t, %1; cvt.u32.u64 %0, t; }" : "=r"(a) : "l"(p));
    return a;
}
__device__ __forceinline__ void split2(float x0, float x1, uint32_t& h, uint32_t& l) {
    __half2 hh = __floats2half2_rn(x0, x1);
    float2 hf = __half22float2(hh);
    __half2 ll = __floats2half2_rn(x0 - hf.x, x1 - hf.y);
    h = *reinterpret_cast<uint32_t*>(&hh);
    l = *reinterpret_cast<uint32_t*>(&ll);
}
__device__ __forceinline__ void mma16(float d[4], const uint32_t a[4],
                                      uint32_t b0, uint32_t b1) {
    asm volatile(
        "mma.sync.aligned.m16n8k16.row.col.f32.f16.f16.f32 "
        "{%0,%1,%2,%3}, {%4,%5,%6,%7}, {%8,%9}, {%0,%1,%2,%3};"
        : "+f"(d[0]), "+f"(d[1]), "+f"(d[2]), "+f"(d[3])
        : "r"(a[0]), "r"(a[1]), "r"(a[2]), "r"(a[3]), "r"(b0), "r"(b1));
}
__device__ __forceinline__ void ldm4(uint32_t r[4], uint32_t addr) {
    asm volatile("ldmatrix.sync.aligned.m8n8.x4.shared.b16 {%0,%1,%2,%3}, [%4];"
                 : "=r"(r[0]), "=r"(r[1]), "=r"(r[2]), "=r"(r[3]) : "r"(addr));
}

// smem: 4-slot ring, each slot = one 16-k sub-chunk buffer (rows of 16 halves,
// stride 48B): Ah|Al|Bh|Bl @ 0/6144/12288/18432 within a slot.
#define A_LO_OFF  6144
#define B_HI_OFF  12288
#define B_LO_OFF  18432
#define BUF_BYTES 24576
#define DYN_SMEM  (4 * BUF_BYTES)        // 98304, 2 CTAs/SM (196.6KB of 228KB)

// ========== R12 GEMM core + 4-slot ring (sync every 2 sub-chunks) ============
__global__ __launch_bounds__(256, 2)
void gemm_mma(const float* __restrict__ A,
              const float* __restrict__ Wt0, const float* __restrict__ Wt1,
              const float* __restrict__ bias0, const float* __restrict__ bias1,
              const float* __restrict__ w00, const float* __restrict__ w01,
              const float* __restrict__ tg, int tIdx,
              float* __restrict__ C, int N, int K, int relu,
              int halfBlocks, int wrapA)
{
    extern __shared__ uint32_t smw[];
    char* smc = (char*)smw;
    const uint32_t smemBase = smem_u32(smw);

    const int tid    = threadIdx.x;
    const int lane   = tid & 31;
    const int wid    = tid >> 5;
    const int warp_m = wid & 3;
    const int warp_n = wid >> 2;
    const int mBase  = blockIdx.y * 128;
    const int nBase  = blockIdx.x * 128;
    const bool hiH   = (int)blockIdx.y >= halfBlocks;
    const float* Wt   = hiH ? Wt1   : Wt0;
    const float* bias = hiH ? bias1 : bias0;
    const float* w0   = hiH ? w01   : w00;

    const int qrow = lane >> 2;
    const int qk   = lane & 3;

    float acc[2][8][4];
#pragma unroll
    for (int i = 0; i < 2; ++i)
#pragma unroll
        for (int j = 0; j < 8; ++j)
#pragma unroll
            for (int q = 0; q < 4; ++q) acc[i][j][q] = 0.f;

    const int r0  = tid >> 2;
    const int r1  = r0 + 64;
    const int c40 = (tid & 3) << 2;
    int ar0 = mBase + r0, ar1 = mBase + r1;
    if (wrapA) { ar0 &= (BSZ - 1); ar1 &= (BSZ - 1); }
    const int gn0 = nBase + r0, gn1 = nBase + r1;

    const int l15 = lane & 15;
    const int lc  = (lane >> 4) << 4;
    const uint32_t offA0 = (uint32_t)(warp_m * 32 + l15) * 48 + lc;
    const uint32_t offA1 = offA0 + 16 * 48;
    const uint32_t offB  = (uint32_t)B_HI_OFF + (uint32_t)(warp_n * 64 + l15) * 48 + lc;

    const int nChunks = (K + 15) >> 4;

    float4 av0, av1, bv0, bv1;
    auto prefetch = [&](int kc) {
        const int gc = (kc << 4) + c40;
        av0 = av1 = bv0 = bv1 = make_float4(0.f, 0.f, 0.f, 0.f);
        if (gc < K) {
            av0 = *(const float4*)(A + (size_t)ar0 * K + gc);
            av1 = *(const float4*)(A + (size_t)ar1 * K + gc);
            if (gn0 < N) bv0 = *(const float4*)(Wt + (size_t)gn0 * K + gc);
            if (gn1 < N) bv1 = *(const float4*)(Wt + (size_t)gn1 * K + gc);
        }
    };
    auto store = [&](int slot) {
        char* buf = smc + slot * BUF_BYTES;
        const uint32_t rowOff0 = (uint32_t)r0 * 48 + c40 * 2;
        const uint32_t rowOff1 = (uint32_t)r1 * 48 + c40 * 2;
        uint32_t h0, l0, h1, l1;
        split2(av0.x, av0.y, h0, l0); split2(av0.z, av0.w, h1, l1);
        *(uint2*)(buf + rowOff0)            = make_uint2(h0, h1);
        *(uint2*)(buf + A_LO_OFF + rowOff0) = make_uint2(l0, l1);
        split2(av1.x, av1.y, h0, l0); split2(av1.z, av1.w, h1, l1);
        *(uint2*)(buf + rowOff1)            = make_uint2(h0, h1);
        *(uint2*)(buf + A_LO_OFF + rowOff1) = make_uint2(l0, l1);
        split2(bv0.x, bv0.y, h0, l0); split2(bv0.z, bv0.w, h1, l1);
        *(uint2*)(buf + B_HI_OFF + rowOff0) = make_uint2(h0, h1);
        *(uint2*)(buf + B_LO_OFF + rowOff0) = make_uint2(l0, l1);
        split2(bv1.x, bv1.y, h0, l0); split2(bv1.z, bv1.w, h1, l1);
        *(uint2*)(buf + B_HI_OFF + rowOff1) = make_uint2(h0, h1);
        *(uint2*)(buf + B_LO_OFF + rowOff1) = make_uint2(l0, l1);
    };

    // prologue: fill slots 0 and 1 (sub-chunks 0, 1)
    prefetch(0);
    store(0);
    if (nChunks > 1) { prefetch(1); store(1); }

    for (int kc = 0; kc < nChunks; ++kc) {
        if (!(kc & 1)) __syncthreads();   // barrier once per slot-pair
        const bool more = (kc + 2 < nChunks);
        if (more) prefetch(kc + 2);

        const uint32_t base = smemBase + (kc & 3) * BUF_BYTES;

        uint32_t ax0[4], ax1[4], bb[4][4];
        // pass 1: Ah * Bh (bh resident)
        ldm4(ax0, base + offA0);
        ldm4(ax1, base + offA1);
#pragma unroll
        for (int t = 0; t < 4; ++t) ldm4(bb[t], base + offB + t * (16 * 48));
#pragma unroll
        for (int t = 0; t < 4; ++t) {
            mma16(acc[0][2 * t],     ax0, bb[t][0], bb[t][2]);
            mma16(acc[1][2 * t],     ax1, bb[t][0], bb[t][2]);
            mma16(acc[0][2 * t + 1], ax0, bb[t][1], bb[t][3]);
            mma16(acc[1][2 * t + 1], ax1, bb[t][1], bb[t][3]);
        }
        // pass 2: Al * Bh
        {
            uint32_t al0[4], al1[4];
            ldm4(al0, base + offA0 + A_LO_OFF);
            ldm4(al1, base + offA1 + A_LO_OFF);
#pragma unroll
            for (int t = 0; t < 4; ++t) {
                mma16(acc[0][2 * t],     al0, bb[t][0], bb[t][2]);
                mma16(acc[1][2 * t],     al1, bb[t][0], bb[t][2]);
                mma16(acc[0][2 * t + 1], al0, bb[t][1], bb[t][3]);
                mma16(acc[1][2 * t + 1], al1, bb[t][1], bb[t][3]);
            }
        }
        // pass 3: Ah * Bl
#pragma unroll
        for (int t = 0; t < 4; ++t)
            ldm4(bb[t], base + offB + (B_LO_OFF - B_HI_OFF) + t * (16 * 48));
#pragma unroll
        for (int t = 0; t < 4; ++t) {
            mma16(acc[0][2 * t],     ax0, bb[t][0], bb[t][2]);
            mma16(acc[1][2 * t],     ax1, bb[t][0], bb[t][2]);
            mma16(acc[0][2 * t + 1], ax0, bb[t][1], bb[t][3]);
            mma16(acc[1][2 * t + 1], ax1, bb[t][1], bb[t][3]);
        }

        if (more) store((kc + 2) & 3);
    }

    // ---------------- epilogue ----------------
    const float tval = w0 ? __ldg(tg + tIdx) : 0.f;
#pragma unroll
    for (int jn = 0; jn < 8; ++jn) {
        int c = nBase + warp_n * 64 + jn * 8 + 2 * qk;
        if (c >= N) continue;
        float b0e = 0.f, b1e = 0.f;
        if (bias) { b0e = __ldg(bias + c); b1e = __ldg(bias + c + 1); }
        if (w0)   { b0e += tval * __ldg(w0 + c); b1e += tval * __ldg(w0 + c + 1); }
#pragma unroll
        for (int im = 0; im < 2; ++im) {
            int r = mBase + warp_m * 32 + im * 16 + qrow;
            float o00 = acc[im][jn][0] + b0e, o01 = acc[im][jn][1] + b1e;
            float o10 = acc[im][jn][2] + b0e, o11 = acc[im][jn][3] + b1e;
            if (relu) {
                o00 = fmaxf(o00, 0.f); o01 = fmaxf(o01, 0.f);
                o10 = fmaxf(o10, 0.f); o11 = fmaxf(o11, 0.f);
            }
            *(float2*)(C + (size_t)r * N + c)       = make_float2(o00, o01);
            *(float2*)(C + (size_t)(r + 8) * N + c) = make_float2(o10, o11);
        }
    }
}

// ---------------- fused weight transposes (ONE launch) ----------------
#define WT_TOTAL (25600 * 2 + 196608 * 2 + 25600 * 2 + DIMN)
__global__ void wtrans_all(const float* __restrict__ Wg_in, const float* __restrict__ Wv_in,
                           const float* __restrict__ Wg_h,  const float* __restrict__ Wv_h,
                           const float* __restrict__ Wg_out, const float* __restrict__ Wv_out,
                           const float* __restrict__ bv_out)
{
    for (int i = blockIdx.x * blockDim.x + threadIdx.x; i < WT_TOTAL;
         i += gridDim.x * blockDim.x) {
        int j = i;
        if (j < 25600) {                       // Wg_in (101x256, skip row 0) -> [256][100]
            int n = j / 100, k = j % 100;
            g_Wgt_in[j] = Wg_in[(size_t)(k + 1) * WH + n];
        } else if ((j -= 25600) < 25600) {     // Wv_in
            int n = j / 100, k = j % 100;
            g_Wvt_in[j] = Wv_in[(size_t)(k + 1) * WH + n];
        } else if ((j -= 25600) < 196608) {    // Wg_h
            int l = j / 65536, r = j % 65536;
            int n = r / 256, k = r % 256;
            (&g_Wgt_h[0][0])[j] = Wg_h[(size_t)l * 65536 + (size_t)k * WH + n];
        } else if ((j -= 196608) < 196608) {   // Wv_h
            int l = j / 65536, r = j % 65536;
            int n = r / 256, k = r % 256;
            (&g_Wvt_h[0][0])[j] = Wv_h[(size_t)l * 65536 + (size_t)k * WH + n];
        } else if ((j -= 196608) < 25600) {    // Wg_out (256x100) -> [100][256]
            int n = j / 256, k = j % 256;
            g_Wgt_out[j] = Wg_out[(size_t)k * DIMN + n];
        } else if ((j -= 25600) < 25600) {     // Wv_out (256x1) -> row 0 of [100][256]
            int n = j / 256, k = j % 256;
            g_Wvt_out[j] = (n == 0) ? Wv_out[k] : 0.f;
        } else {                               // bvout padded bias
            j -= 25600;
            g_bvout[j] = (j == 0) ? bv_out[0] : 0.f;
        }
    }
}

// ---------------- step (+ previous-step error, vsave) ----------------
__global__ __launch_bounds__(256) void step_err(
    const float* __restrict__ S_old, const float* __restrict__ vp,
    const float* __restrict__ grad, const float* __restrict__ Cv,
    const float* __restrict__ tg, int i,
    float* __restrict__ S_new, float* __restrict__ stoch,
    float* __restrict__ vsave, float* __restrict__ err)
{
    int warp = threadIdx.x >> 5, lane = threadIdx.x & 31;
    int b = blockIdx.x * 8 + warp;
    float h  = tg[i + 1] - tg[i];
    float sq = sqrtf(h);
    float rh = RRATE * h;
    if (lane == 0) {
        float vC = Cv[(size_t)b * DIMN];
        if (i > 0) {
            float hp = tg[i] - tg[i - 1];
            float e = vC - vsave[b] * (1.f + RRATE * hp) - stoch[b];
            err[b] += e * e;
        }
        vsave[b] = vC;
    }
    const float* Sr = S_old + (size_t)b * DIMN;
    const float* vr = vp   + (size_t)b * DIMN;
    const float* gr = grad + (size_t)b * DIMN;
    float acc = 0.f;
    for (int d = lane; d < DIMN; d += 32) {
        float s   = Sr[d];
        float vol = s * (vr[d] * sq);
        acc += gr[d] * vol;
        S_new[(size_t)b * DIMN + d] = s + rh * s + vol;
    }
#pragma unroll
    for (int o = 16; o; o >>= 1) acc += __shfl_xor_sync(0xffffffffu, acc, o);
    if (lane == 0) stoch[b] = acc;
}

// ---------------- output packing + final error term ----------------
__global__ void pack_kernel(const float* __restrict__ Cv, const float* __restrict__ S,
                            const float* __restrict__ vsave, const float* __restrict__ stoch,
                            const float* __restrict__ tg, const float* __restrict__ err,
                            float* __restrict__ out)
{
    int i = blockIdx.x * 256 + threadIdx.x;
    if (i < BSZ * DIMN) out[BSZ + i] = S[i];
    if (i < BSZ) {
        float vC = Cv[(size_t)i * DIMN];
        float hp = tg[NSTEP] - tg[NSTEP - 1];
        float e = vC - vsave[i] * (1.f + RRATE * hp) - stoch[i];
        out[i] = vC;
        out[BSZ + BSZ * DIMN + i] = err[i] + e * e;
    }
}

extern "C" void kernel_launch(void* const* d_in, const int* in_sizes, int n_in,
                              void* d_out, int out_size)
{
    const float* S0     = (const float*)d_in[0];
    const float* dW     = (const float*)d_in[1];
    const float* tg     = (const float*)d_in[2];
    const float* Vm     = (const float*)d_in[3];
    const float* Wg_in  = (const float*)d_in[4];
    const float* bg_in  = (const float*)d_in[5];
    const float* Wg_h   = (const float*)d_in[6];
    const float* bg_h   = (const float*)d_in[7];
    const float* Wg_out = (const float*)d_in[8];
    const float* bg_out = (const float*)d_in[9];
    const float* Wv_in  = (const float*)d_in[10];
    const float* bv_in  = (const float*)d_in[11];
    const float* Wv_h   = (const float*)d_in[12];
    const float* bv_h   = (const float*)d_in[13];
    const float* Wv_out = (const float*)d_in[14];
    const float* bv_out = (const float*)d_in[15];

    cudaFuncSetAttribute(gemm_mma, cudaFuncAttributeMaxDynamicSharedMemorySize,
                         DYN_SMEM);

    float *volpre, *Sb, *hd, *Cbuf, *vsave, *stoch, *err, *bvout;
    float *Wgt_in, *Wgt_h, *Wgt_out, *Wvt_out, *Wvt_in, *Wvt_h;
    cudaGetSymbolAddress((void**)&volpre, g_volpre);
    cudaGetSymbolAddress((void**)&Sb,     g_Sbuf);
    cudaGetSymbolAddress((void**)&hd,     g_hdual);
    cudaGetSymbolAddress((void**)&Cbuf,   g_C);
    cudaGetSymbolAddress((void**)&vsave,  g_vsave);
    cudaGetSymbolAddress((void**)&stoch,  g_stoch);
    cudaGetSymbolAddress((void**)&err,    g_err);
    cudaGetSymbolAddress((void**)&bvout,  g_bvout);
    cudaGetSymbolAddress((void**)&Wgt_in, g_Wgt_in);
    cudaGetSymbolAddress((void**)&Wgt_h,  g_Wgt_h);
    cudaGetSymbolAddress((void**)&Wgt_out,g_Wgt_out);
    cudaGetSymbolAddress((void**)&Wvt_out,g_Wvt_out);
    cudaGetSymbolAddress((void**)&Wvt_in, g_Wvt_in);
    cudaGetSymbolAddress((void**)&Wvt_h,  g_Wvt_h);

    float* Sbuf0 = Sb;
    float* Sbuf1 = Sb + (size_t)BSZ * DIMN;
    float* hA = hd;
    float* hB = hd + (size_t)2 * BSZ * WH;
    float* Cv = Cbuf + (size_t)BSZ * DIMN;

    // launch 0: weight transposes
    wtrans_all<<<512, 256>>>(Wg_in, Wv_in, Wg_h, Wv_h, Wg_out, Wv_out, bv_out);

    // launch 1: volpre = dW @ V^T (B operand is V itself, [N,K] K-major)
    {
        dim3 grid(1, (NSTEP * BSZ) / 128);
        gemm_mma<<<grid, 256, DYN_SMEM>>>(dW, Vm, Vm, nullptr, nullptr,
                                          nullptr, nullptr, nullptr, 0,
                                          volpre, DIMN, DIMN, 0, 1 << 30, 0);
    }

    auto dual_trunk = [&](const float* S, int tIdx) {
        dim3 grid(2, 128);
        gemm_mma<<<grid, 256, DYN_SMEM>>>(S, Wgt_in, Wvt_in, bg_in, bv_in,
                                          Wg_in, Wv_in, tg, tIdx,
                                          hA, WH, DIMN, 1, 64, 1);
        gemm_mma<<<grid, 256, DYN_SMEM>>>(hA, Wgt_h, Wvt_h, bg_h, bv_h,
                                          nullptr, nullptr, nullptr, 0,
                                          hB, WH, WH, 1, 64, 0);
        gemm_mma<<<grid, 256, DYN_SMEM>>>(hB, Wgt_h + 65536, Wvt_h + 65536,
                                          bg_h + WH, bv_h + WH,
                                          nullptr, nullptr, nullptr, 0,
                                          hA, WH, WH, 1, 64, 0);
        gemm_mma<<<grid, 256, DYN_SMEM>>>(hA, Wgt_h + 2 * 65536, Wvt_h + 2 * 65536,
                                          bg_h + 2 * WH, bv_h + 2 * WH,
                                          nullptr, nullptr, nullptr, 0,
                                          hB, WH, WH, 1, 64, 0);
    };
    auto gradv = [&]() {   // grad rows 0..8191 (g out-weights), v rows 8192.. (v out col 0)
        dim3 grid(1, 128);
        gemm_mma<<<grid, 256, DYN_SMEM>>>(hB, Wgt_out, Wvt_out, bg_out, bvout,
                                          nullptr, nullptr, nullptr, 0,
                                          Cbuf, DIMN, WH, 0, 64, 0);
    };

    // initial trunk on [t0, S0]
    dual_trunk(S0, 0);
    gradv();                                      // grad_0, v_0
    cudaMemsetAsync(err, 0, BSZ * sizeof(float));

    const float* Scur = S0;
    int sflip = 0;
    for (int i = 0; i < NSTEP; ++i) {
        float* Snew = sflip ? Sbuf1 : Sbuf0;
        step_err<<<BSZ / 8, 256>>>(Scur, volpre + (size_t)i * BSZ * DIMN,
                                   Cbuf, Cv, tg, i, Snew, stoch, vsave, err);
        dual_trunk(Snew, i + 1);
        gradv();                                  // grad_{i+1}, v_{i+1}
        Scur = Snew; sflip ^= 1;
    }

    pack_kernel<<<(BSZ * DIMN) / 256, 256>>>(Cv, Scur, vsave, stoch, tg, err,
                                             (float*)d_out);
}